// round 1
// baseline (speedup 1.0000x reference)
#include <cuda_runtime.h>
#include <cstdint>
#include <cstdio>

#define DTc 0.0005f
#define SPFc 10
#define Bc 25
#define NBc 26
#define WPB 4   // warps (= batch elements) per block

// per-warp staging buffer layout (floats)
#define OFF_TAU 0      // 10*31 = 310
#define OFF_REF 310    // 10*25 = 250
#define OFF_RFR 560    // 10*6  = 60
#define OFF_RFJ 620    // 10*75 = 750
#define BUF_FLOATS 1370

__device__ __forceinline__ void cp4(float* dst, const float* src) {
    unsigned d = (unsigned)__cvta_generic_to_shared(dst);
    asm volatile("cp.async.ca.shared.global [%0], [%1], 4;\n" :: "r"(d), "l"(src));
}
__device__ __forceinline__ void cp_commit() { asm volatile("cp.async.commit_group;\n"); }
__device__ __forceinline__ void cp_wait0()  { asm volatile("cp.async.wait_group 0;\n"); }

__device__ __forceinline__ void quat_mul(
    float ax, float ay, float az, float aw,
    float bx, float by, float bz, float bw,
    float& rx, float& ry, float& rz, float& rw)
{
    rx = aw*bx + ax*bw + ay*bz - az*by;
    ry = aw*by - ax*bz + ay*bw + az*bx;
    rz = aw*bz + ax*by - ay*bx + az*bw;
    rw = aw*bw - ax*bx - ay*by - az*bz;
}

__device__ __forceinline__ void quat_rot(
    float qx, float qy, float qz, float qw,
    float vx, float vy, float vz,
    float& rx, float& ry, float& rz)
{
    float tx = 2.f*(qy*vz - qz*vy);
    float ty = 2.f*(qz*vx - qx*vz);
    float tz = 2.f*(qx*vy - qy*vx);
    rx = vx + qw*tx + (qy*tz - qz*ty);
    ry = vy + qw*ty + (qz*tx - qx*tz);
    rz = vz + qw*tz + (qx*ty - qy*tx);
}

// 3-vector inclusive warp prefix sum
#define SCAN3(X, Y, Z, lane)                                              \
    _Pragma("unroll")                                                     \
    for (int _o = 1; _o < 32; _o <<= 1) {                                 \
        float _tx = __shfl_up_sync(0xffffffffu, X, _o);                   \
        float _ty = __shfl_up_sync(0xffffffffu, Y, _o);                   \
        float _tz = __shfl_up_sync(0xffffffffu, Z, _o);                   \
        if ((lane) >= _o) { X += _tx; Y += _ty; Z += _tz; }               \
    }

// Forward kinematics over the 25-joint chain via warp scans, write one frame.
__device__ __forceinline__ void fk_emit(
    float* __restrict__ out, size_t posBase, size_t velBase, int lane,
    float px, float py, float pz,
    float qx, float qy, float qz, float qw,
    float wx, float wy, float wz,
    float vx, float vy, float vz,
    float jq, float jqd,
    float ax, float ay, float az,
    float ox, float oy, float oz)
{
    // local joint rotation dq  (lanes >= Bc: axis = 0, jq = 0 -> identity)
    float sh, ch;
    sincosf(0.5f * jq, &sh, &ch);
    float Px = ax*sh, Py = ay*sh, Pz = az*sh, Pw = ch;

    // inclusive quaternion product scan: lane j -> dq_0 * ... * dq_j
    #pragma unroll
    for (int o = 1; o < 32; o <<= 1) {
        float bx = __shfl_up_sync(0xffffffffu, Px, o);
        float by = __shfl_up_sync(0xffffffffu, Py, o);
        float bz = __shfl_up_sync(0xffffffffu, Pz, o);
        float bw = __shfl_up_sync(0xffffffffu, Pw, o);
        if (lane >= o) {
            float rx, ry, rz, rw;
            quat_mul(bx, by, bz, bw, Px, Py, Pz, Pw, rx, ry, rz, rw);
            Px = rx; Py = ry; Pz = rz; Pw = rw;
        }
    }
    // exclusive product (parent-of-lane-j accumulated rotation)
    float Ex = __shfl_up_sync(0xffffffffu, Px, 1);
    float Ey = __shfl_up_sync(0xffffffffu, Py, 1);
    float Ez = __shfl_up_sync(0xffffffffu, Pz, 1);
    float Ew = __shfl_up_sync(0xffffffffu, Pw, 1);
    if (lane == 0) { Ex = 0.f; Ey = 0.f; Ez = 0.f; Ew = 1.f; }

    // parent world rotation and child world rotation
    float Qpx, Qpy, Qpz, Qpw, Qcx, Qcy, Qcz, Qcw;
    quat_mul(qx, qy, qz, qw, Ex, Ey, Ez, Ew, Qpx, Qpy, Qpz, Qpw);
    quat_mul(qx, qy, qz, qw, Px, Py, Pz, Pw, Qcx, Qcy, Qcz, Qcw);

    // world-frame offset and joint axis (zero for lanes >= Bc since off/axis = 0)
    float owx, owy, owz, awx, awy, awz;
    quat_rot(Qpx, Qpy, Qpz, Qpw, ox, oy, oz, owx, owy, owz);
    quat_rot(Qpx, Qpy, Qpz, Qpw, ax, ay, az, awx, awy, awz);
    float dwx = awx * jqd, dwy = awy * jqd, dwz = awz * jqd;

    // w prefix
    float Wx = dwx, Wy = dwy, Wz = dwz;
    SCAN3(Wx, Wy, Wz, lane);
    float wpx = wx + (Wx - dwx);   // parent w
    float wpy = wy + (Wy - dwy);
    float wpz = wz + (Wz - dwz);

    // dv = cross(parent w, off_w)
    float dvx = wpy*owz - wpz*owy;
    float dvy = wpz*owx - wpx*owz;
    float dvz = wpx*owy - wpy*owx;

    // p prefix (consumes ow), v prefix
    float Sx = owx, Sy = owy, Sz = owz;
    SCAN3(Sx, Sy, Sz, lane);
    float Vx = dvx, Vy = dvy, Vz = dvz;
    SCAN3(Vx, Vy, Vz, lane);

    if (lane == 0) {
        out[posBase + 0] = px; out[posBase + 1] = py; out[posBase + 2] = pz;
        out[posBase + 3] = qx; out[posBase + 4] = qy; out[posBase + 5] = qz; out[posBase + 6] = qw;
        out[velBase + 0] = wx; out[velBase + 1] = wy; out[velBase + 2] = wz;
        out[velBase + 3] = vx; out[velBase + 4] = vy; out[velBase + 5] = vz;
    }
    if (lane < Bc) {
        size_t pb = posBase + (size_t)(1 + lane) * 7;
        out[pb + 0] = px + Sx; out[pb + 1] = py + Sy; out[pb + 2] = pz + Sz;
        out[pb + 3] = Qcx; out[pb + 4] = Qcy; out[pb + 5] = Qcz; out[pb + 6] = Qcw;
        size_t vb = velBase + (size_t)(1 + lane) * 6;
        out[vb + 0] = wx + Wx; out[vb + 1] = wy + Wy; out[vb + 2] = wz + Wz;
        out[vb + 3] = vx + Vx; out[vb + 4] = vy + Vy; out[vb + 5] = vz + Vz;
    }
}

__device__ __forceinline__ void stage_frame(
    float* __restrict__ buf, int lane, int f, int b, int bs,
    const float* __restrict__ torques,
    const float* __restrict__ refs,
    const float* __restrict__ res_f)
{
    const int s0 = f * SPFc;
    #pragma unroll
    for (int s = 0; s < SPFc; s++) {
        const float* rT = torques + ((size_t)(s0 + s) * bs + b) * 31;
        const float* rR = refs    + ((size_t)(s0 + s) * bs + b) * 31;
        const float* rF = res_f   + ((size_t)(s0 + s) * bs + b) * 156;
        if (lane < 31) cp4(buf + OFF_TAU + s*31 + lane, rT + lane);
        if (lane < 25) cp4(buf + OFF_REF + s*25 + lane, rR + 6 + lane);
        if (lane < 6)  cp4(buf + OFF_RFR + s*6  + lane, rF + lane);
        #pragma unroll
        for (int k = 0; k < 3; k++) {
            int idx = k * 32 + lane;
            if (idx < 75) {
                int j = idx / 3, c = idx - 3 * j;
                cp4(buf + OFF_RFJ + s*75 + idx, rF + 6 + j*6 + c);
            }
        }
    }
}

__global__ void __launch_bounds__(32 * WPB)
phys_kernel(
    const float* __restrict__ q_init, const float* __restrict__ qd_init,
    const float* __restrict__ torques, const float* __restrict__ res_f,
    const float* __restrict__ refs, const float* __restrict__ tke,
    const float* __restrict__ tkd, const float* __restrict__ bmass,
    const float* __restrict__ jaxes, const float* __restrict__ joffs,
    float* __restrict__ out, int bs, int F)
{
    __shared__ float sbuf[WPB][2][BUF_FLOATS];
    const int warp = threadIdx.x >> 5;
    const int lane = threadIdx.x & 31;
    const int b = blockIdx.x * WPB + warp;
    if (b >= bs) return;
    const int ND = 7 + Bc;   // 32
    const int NDD = 6 + Bc;  // 31

    // ---- init root state (replicated in all lanes; uniform broadcast loads) ----
    float px = q_init[b*ND + 0], py = q_init[b*ND + 1], pz = q_init[b*ND + 2];
    float qx = q_init[b*ND + 3], qy = q_init[b*ND + 4], qz = q_init[b*ND + 5], qw = q_init[b*ND + 6];
    {
        float n2 = qx*qx + qy*qy + qz*qz + qw*qw;
        float inv = rsqrtf(fmaxf(n2, 1e-16f));
        qx *= inv; qy *= inv; qz *= inv; qw *= inv;
    }
    float wx = qd_init[b*NDD + 0], wy = qd_init[b*NDD + 1], wz = qd_init[b*NDD + 2];
    float vx = qd_init[b*NDD + 3], vy = qd_init[b*NDD + 4], vz = qd_init[b*NDD + 5];
    const float invm0 = 1.f / (bmass[b*NBc + 0] + 0.1f);

    // ---- init per-joint state (lane j) ----
    float jq = 0.f, jqd = 0.f, ke = 0.f, kd = 0.f, invmj = 0.f;
    float ax = 0.f, ay = 0.f, az = 0.f, ox = 0.f, oy = 0.f, oz = 0.f;
    if (lane < Bc) {
        jq   = q_init[b*ND + 7 + lane];
        jqd  = qd_init[b*NDD + 6 + lane];
        ke   = tke[b*Bc + lane];
        kd   = tkd[b*Bc + lane];
        invmj = 1.f / (bmass[b*NBc + 1 + lane] + 0.1f);
        float a0 = jaxes[lane*3 + 0], a1 = jaxes[lane*3 + 1], a2 = jaxes[lane*3 + 2];
        float n = fmaxf(sqrtf(a0*a0 + a1*a1 + a2*a2), 1e-8f);
        ax = a0 / n; ay = a1 / n; az = a2 / n;
        ox = joffs[lane*3 + 0]; oy = joffs[lane*3 + 1]; oz = joffs[lane*3 + 2];
    }

    const size_t posStride = (size_t)bs * NBc * 7;
    const size_t velStride = (size_t)bs * NBc * 6;
    const size_t POS_TOTAL = (size_t)(F + 1) * posStride;
    const size_t pb0 = (size_t)b * NBc * 7;
    const size_t vb0 = (size_t)b * NBc * 6;

    // frame 0 FK (initial state)
    fk_emit(out, pb0, POS_TOTAL + vb0, lane,
            px, py, pz, qx, qy, qz, qw, wx, wy, wz, vx, vy, vz,
            jq, jqd, ax, ay, az, ox, oy, oz);

    float* buf0 = &sbuf[warp][0][0];
    float* buf1 = &sbuf[warp][1][0];

    stage_frame(buf0, lane, 0, b, bs, torques, refs, res_f);
    cp_commit();
    cp_wait0();
    __syncwarp();

    for (int f = 0; f < F; f++) {
        float* cur = (f & 1) ? buf1 : buf0;
        float* nxt = (f & 1) ? buf0 : buf1;
        if (f + 1 < F) {
            stage_frame(nxt, lane, f + 1, b, bs, torques, refs, res_f);
            cp_commit();
        }

        #pragma unroll
        for (int s = 0; s < SPFc; s++) {
            const float* tau = cur + OFF_TAU + s * 31;
            const float* rfr = cur + OFF_RFR + s * 6;
            // root linear/angular velocity
            vx += DTc * ((tau[3] + rfr[3]) * invm0);
            vy += DTc * ((tau[4] + rfr[4]) * invm0);
            vz += DTc * ((tau[5] + rfr[5]) * invm0 - 9.81f);
            wx += DTc * ((tau[0] + rfr[0]) * invm0);
            wy += DTc * ((tau[1] + rfr[1]) * invm0);
            wz += DTc * ((tau[2] + rfr[2]) * invm0);
            px += DTc * vx;
            py += DTc * vy;
            pz += DTc * vz;
            // quaternion integration: q += 0.5*dt*quat_mul((w,0), q); normalize
            float mx =  wx*qw + wy*qz - wz*qy;
            float my = -wx*qz + wy*qw + wz*qx;
            float mz =  wx*qy - wy*qx + wz*qw;
            float mw = -(wx*qx + wy*qy + wz*qz);
            qx += 0.5f * DTc * mx;
            qy += 0.5f * DTc * my;
            qz += 0.5f * DTc * mz;
            qw += 0.5f * DTc * mw;
            float n2 = qx*qx + qy*qy + qz*qz + qw*qw;
            float inv = rsqrtf(fmaxf(n2, 1e-16f));
            qx *= inv; qy *= inv; qz *= inv; qw *= inv;
            // joints
            if (lane < Bc) {
                float tj = tau[6 + lane];
                float rj = cur[OFF_REF + s*25 + lane];
                float gx = cur[OFF_RFJ + s*75 + lane*3 + 0];
                float gy = cur[OFF_RFJ + s*75 + lane*3 + 1];
                float gz = cur[OFF_RFJ + s*75 + lane*3 + 2];
                float tq = tj + ke * (rj - jq) - kd * jqd + (gx*ax + gy*ay + gz*az);
                jqd += DTc * tq * invmj;
                jq  += DTc * jqd;
            }
        }

        fk_emit(out,
                (size_t)(f + 1) * posStride + pb0,
                POS_TOTAL + (size_t)(f + 1) * velStride + vb0,
                lane,
                px, py, pz, qx, qy, qz, qw, wx, wy, wz, vx, vy, vz,
                jq, jqd, ax, ay, az, ox, oy, oz);

        if (f + 1 < F) {
            cp_wait0();
            __syncwarp();
        }
    }
}

extern "C" void kernel_launch(void* const* d_in, const int* in_sizes, int n_in,
                              void* d_out, int out_size)
{
    const float* q_init   = (const float*)d_in[0];
    const float* qd_init  = (const float*)d_in[1];
    const float* torques  = (const float*)d_in[2];
    const float* res_f    = (const float*)d_in[3];
    const float* refs     = (const float*)d_in[4];
    const float* tke      = (const float*)d_in[5];
    const float* tkd      = (const float*)d_in[6];
    const float* bmass    = (const float*)d_in[7];
    const float* jaxes    = (const float*)d_in[8];
    const float* joffs    = (const float*)d_in[9];
    float* out = (float*)d_out;

    const int B = in_sizes[8] / 3;                 // 25
    const int bs = in_sizes[0] / (7 + B);          // 1024
    const int S = in_sizes[2] / (bs * (6 + B));    // 150
    const int F = S / SPFc;                        // 15

    const int blocks = (bs + WPB - 1) / WPB;
    phys_kernel<<<blocks, 32 * WPB>>>(q_init, qd_init, torques, res_f, refs,
                                      tke, tkd, bmass, jaxes, joffs,
                                      out, bs, F);
}